// round 9
// baseline (speedup 1.0000x reference)
#include <cuda_runtime.h>
#include <cuda_bf16.h>
#include <mma.h>
#include <math.h>
#include <float.h>
#include <stdint.h>

using namespace nvcuda;

#define Bc 2
#define Lc 1024
#define Dc 1024
#define Hc 16
#define NL 8
#define Vc 32000
#define Fc 4096
#define DHc 64

// ---------------------------------------------------------------------------
// Device-global scratch
// ---------------------------------------------------------------------------
__device__ float g_y[Bc*Lc*Dc];
__device__ float g_qkv[Bc*Lc*3*Dc];
__device__ float g_att[Bc*Hc*Lc*Lc];
__device__ float g_gp[Bc*Lc*2*Fc];
// bf16 hi/lo planes
__device__ __nv_bfloat16 g_xh[Bc*Lc*Dc],  g_xl[Bc*Lc*Dc];
__device__ __nv_bfloat16 g_qh[Bc*Lc*Dc],  g_ql[Bc*Lc*Dc];
__device__ __nv_bfloat16 g_kh[Bc*Lc*Dc],  g_kl[Bc*Lc*Dc];
__device__ __nv_bfloat16 g_vth[Bc*Hc*DHc*Lc], g_vtl[Bc*Hc*DHc*Lc];
__device__ __nv_bfloat16 g_th[Bc*Lc*Dc],  g_tl[Bc*Lc*Dc];
__device__ __nv_bfloat16 g_ph[Bc*Hc*Lc*Lc], g_pl[Bc*Hc*Lc*Lc];
__device__ __nv_bfloat16 g_gh[Bc*Lc*Fc],  g_gl[Bc*Lc*Fc];
__device__ __nv_bfloat16 g_wh[166985728], g_wl[166985728];

__device__ __forceinline__ uint32_t packf(float v) {
    __nv_bfloat16 h = __float2bfloat16(v);
    float hf = __bfloat162float(h);
    __nv_bfloat16 l = __float2bfloat16(v - hf);
    return (uint32_t)__bfloat16_as_ushort(h) | ((uint32_t)__bfloat16_as_ushort(l) << 16);
}
__device__ __forceinline__ void packf2(float v, __nv_bfloat16& h, __nv_bfloat16& l) {
    h = __float2bfloat16(v);
    l = __float2bfloat16(v - __bfloat162float(h));
}

__device__ __forceinline__ uint32_t smem_u32(const void* p) {
    uint32_t a;
    asm("{ .reg .u64 t; cvta.to.shared.u64 t, %1; cvt.u32.u64 %0, t; }" : "=r"(a) : "l"(p));
    return a;
}
__device__ __forceinline__ void cpasync16(uint32_t dst, const void* src) {
    asm volatile("cp.async.cg.shared.global [%0], [%1], 16;" :: "r"(dst), "l"(src) : "memory");
}
__device__ __forceinline__ void cp_commit() {
    asm volatile("cp.async.commit_group;" ::: "memory");
}
__device__ __forceinline__ void cp_wait1() {
    asm volatile("cp.async.wait_group 1;" ::: "memory");
}

// ---------------------------------------------------------------------------
// Block reductions (blockDim.x == 256)
// ---------------------------------------------------------------------------
__device__ __forceinline__ float blockReduceSum(float v) {
    __shared__ float sh[33];
    int lane = threadIdx.x & 31, wid = threadIdx.x >> 5;
    #pragma unroll
    for (int o = 16; o > 0; o >>= 1) v += __shfl_down_sync(0xffffffffu, v, o);
    if (lane == 0) sh[wid] = v;
    __syncthreads();
    v = (threadIdx.x < 8) ? sh[lane] : 0.0f;
    if (wid == 0) {
        #pragma unroll
        for (int o = 4; o > 0; o >>= 1) v += __shfl_down_sync(0xffffffffu, v, o);
        if (lane == 0) sh[32] = v;
    }
    __syncthreads();
    return sh[32];
}
__device__ __forceinline__ float blockReduceMax(float v) {
    __shared__ float sh[33];
    int lane = threadIdx.x & 31, wid = threadIdx.x >> 5;
    #pragma unroll
    for (int o = 16; o > 0; o >>= 1) v = fmaxf(v, __shfl_down_sync(0xffffffffu, v, o));
    if (lane == 0) sh[wid] = v;
    __syncthreads();
    v = (threadIdx.x < 8) ? sh[lane] : -FLT_MAX;
    if (wid == 0) {
        #pragma unroll
        for (int o = 4; o > 0; o >>= 1) v = fmaxf(v, __shfl_down_sync(0xffffffffu, v, o));
        if (lane == 0) sh[32] = v;
    }
    __syncthreads();
    return sh[32];
}

// ---------------------------------------------------------------------------
// WMMA GEMM, cp.async 2-stage pipeline, 128-thread CTAs (4 warps, 2Mx2N),
// warp tile 64 x (BN/2), 2 CTAs/SM.
// D[M,N] = A[M,K] @ B[N,K]^T, bf16x3 (hi*hi + hi*lo + lo*hi), fp32 accum.
// A,B: separate hi/lo bf16 planes, K-major. BM=128, BK=32.
// flags: bit1 = causal tile skip, bit2 = K clip to row0+128.
// Ch != null -> bf16 hi/lo output planes; else fp32 C (R folded into acc init).
// ---------------------------------------------------------------------------
#define LDS_ 40     // smem row pitch in bf16 elems (64B data + 16B pad)

template<int BN>
__global__ __launch_bounds__(128, 2) void gemm_mma(
    const __nv_bfloat16* __restrict__ Ahp, const __nv_bfloat16* __restrict__ Alp,
    const __nv_bfloat16* __restrict__ Bhp, const __nv_bfloat16* __restrict__ Blp,
    float* __restrict__ C, __nv_bfloat16* __restrict__ Ch, __nv_bfloat16* __restrict__ Cl,
    const float* __restrict__ R,
    int K, int lda, int ldb, int ldc, int bH,
    long sAb, long sAh, long sBb, long sBh, long sCb, long sCh, int flags)
{
    const int BM = 128;
    const int WN = BN / 2;           // warp N span
    const int NT = WN / 16;          // 16-col tiles per warp (4 or 2)
    const int APB = 5120;            // A plane elems in smem (128*40)
    const int BPB = BN * LDS_;
    const int SSZ = (2 * APB + 2 * BPB) * 2;   // stage bytes

    int row0 = blockIdx.y * BM, col0 = blockIdx.x * BN;
    if ((flags & 2) && col0 >= row0 + BM) return;
    if (flags & 4) { int kc = row0 + BM; if (kc < K) K = kc; }
    int z = blockIdx.z, zb = z / bH, zh = z - zb * bH;
    long aoff = (long)zb * sAb + (long)zh * sAh;
    long boff = (long)zb * sBb + (long)zh * sBh;
    long coff = (long)zb * sCb + (long)zh * sCh;

    extern __shared__ __align__(16) char smraw[];
    uint32_t sbase = smem_u32(smraw);

    int tid = threadIdx.x, wid = tid >> 5, lane = tid & 31;
    int wm = wid & 1, wn = wid >> 1;

    wmma::fragment<wmma::accumulator, 16, 16, 16, float> acc[4][NT];
    if (R) {
        const float* Rb = R + coff;
        #pragma unroll
        for (int i = 0; i < 4; i++)
            #pragma unroll
            for (int j = 0; j < NT; j++)
                wmma::load_matrix_sync(acc[i][j],
                    Rb + (long)(row0 + wm * 64 + i * 16) * ldc + col0 + wn * WN + j * 16,
                    ldc, wmma::mem_row_major);
    } else {
        #pragma unroll
        for (int i = 0; i < 4; i++)
            #pragma unroll
            for (int j = 0; j < NT; j++)
                wmma::fill_fragment(acc[i][j], 0.0f);
    }

    const __nv_bfloat16* Ahg = Ahp + aoff + (long)row0 * lda;
    const __nv_bfloat16* Alg = Alp + aoff + (long)row0 * lda;
    const __nv_bfloat16* Bhg = Bhp + boff + (long)col0 * ldb;
    const __nv_bfloat16* Blg = Blp + boff + (long)col0 * ldb;
    int NC = K >> 5;

    auto issue = [&](int c) {
        uint32_t sb = sbase + (c & 1) * SSZ;
        int kc = c << 5;
        #pragma unroll
        for (int i = 0; i < 4; i++) {
            int lin = tid + i * 128;
            int r = lin >> 2, g = lin & 3;
            long go = (long)r * lda + kc + g * 8;
            uint32_t so = r * 80 + g * 16;
            cpasync16(sb + so, Ahg + go);
            cpasync16(sb + 2 * APB + so, Alg + go);
        }
        #pragma unroll
        for (int i = 0; i < BN / 32; i++) {
            int lin = tid + i * 128;
            int r = lin >> 2, g = lin & 3;
            long go = (long)r * ldb + kc + g * 8;
            uint32_t so = r * 80 + g * 16;
            cpasync16(sb + 4 * APB + so, Bhg + go);
            cpasync16(sb + 4 * APB + 2 * BPB + so, Blg + go);
        }
    };

    issue(0); cp_commit();
    if (NC > 1) issue(1);
    cp_commit();

    for (int c = 0; c < NC; c++) {
        cp_wait1();
        __syncthreads();
        {
            const __nv_bfloat16* base = (const __nv_bfloat16*)(smraw + (c & 1) * SSZ);
            const __nv_bfloat16* Ah = base;
            const __nv_bfloat16* Al = base + APB;
            const __nv_bfloat16* Bh = base + 2 * APB;
            const __nv_bfloat16* Bl = base + 2 * APB + BPB;
            #pragma unroll
            for (int ks = 0; ks < 2; ks++) {
                int k0 = ks * 16;
                wmma::fragment<wmma::matrix_b, 16, 16, 16, __nv_bfloat16, wmma::col_major> fbh[NT], fbl[NT];
                #pragma unroll
                for (int j = 0; j < NT; j++) {
                    wmma::load_matrix_sync(fbh[j], Bh + (wn * WN + j * 16) * LDS_ + k0, LDS_);
                    wmma::load_matrix_sync(fbl[j], Bl + (wn * WN + j * 16) * LDS_ + k0, LDS_);
                }
                #pragma unroll
                for (int i = 0; i < 4; i++) {
                    wmma::fragment<wmma::matrix_a, 16, 16, 16, __nv_bfloat16, wmma::row_major> fah, fal;
                    wmma::load_matrix_sync(fah, Ah + (wm * 64 + i * 16) * LDS_ + k0, LDS_);
                    wmma::load_matrix_sync(fal, Al + (wm * 64 + i * 16) * LDS_ + k0, LDS_);
                    #pragma unroll
                    for (int j = 0; j < NT; j++) {
                        wmma::mma_sync(acc[i][j], fah, fbh[j], acc[i][j]);
                        wmma::mma_sync(acc[i][j], fah, fbl[j], acc[i][j]);
                        wmma::mma_sync(acc[i][j], fal, fbh[j], acc[i][j]);
                    }
                }
            }
        }
        __syncthreads();
        if (c + 2 < NC) issue(c + 2);
        cp_commit();
    }

    // ---- epilogue ----
    if (!Ch) {
        float* Cb = C + coff;
        #pragma unroll
        for (int i = 0; i < 4; i++)
            #pragma unroll
            for (int j = 0; j < NT; j++)
                wmma::store_matrix_sync(
                    Cb + (long)(row0 + wm * 64 + i * 16) * ldc + col0 + wn * WN + j * 16,
                    acc[i][j], ldc, wmma::mem_row_major);
    } else {
        __syncthreads();
        float* wbuf = (float*)smraw + wid * 256;
        #pragma unroll
        for (int i = 0; i < 4; i++)
            #pragma unroll
            for (int j = 0; j < NT; j++) {
                wmma::store_matrix_sync(wbuf, acc[i][j], 16, wmma::mem_row_major);
                __syncwarp();
                int r = lane >> 1, chn = lane & 1;
                const float* src = wbuf + r * 16 + chn * 8;
                __nv_bfloat16 hb[8], lb[8];
                #pragma unroll
                for (int t = 0; t < 8; t++) packf2(src[t], hb[t], lb[t]);
                long off = (long)(row0 + wm * 64 + i * 16 + r) * ldc + col0 + wn * WN + j * 16 + chn * 8 + coff;
                *(uint4*)(Ch + off) = *(uint4*)hb;
                *(uint4*)(Cl + off) = *(uint4*)lb;
                __syncwarp();
            }
    }
}

// ---------------------------------------------------------------------------
// Aux kernels
// ---------------------------------------------------------------------------
__global__ void embed_k(const int* __restrict__ tokens, const float* __restrict__ emb,
                        float* __restrict__ y) {
    int r = blockIdx.x;
    int tok = tokens[r];
    const float4* src = (const float4*)(emb + (long)tok * Dc);
    float4* dst = (float4*)(y + (long)r * Dc);
    for (int i = threadIdx.x; i < Dc / 4; i += blockDim.x) dst[i] = src[i];
}

__global__ void rmsnorm_pack(const float* __restrict__ in, const float* __restrict__ w,
                             __nv_bfloat16* __restrict__ oh, __nv_bfloat16* __restrict__ ol) {
    long b = (long)blockIdx.x * Dc;
    float s = 0.0f;
    for (int i = threadIdx.x; i < Dc; i += 256) { float v = in[b + i]; s += v * v; }
    s = blockReduceSum(s);
    float inv = rsqrtf(s * (1.0f / Dc) + 1e-6f);
    for (int i = threadIdx.x; i < Dc; i += 256)
        packf2(in[b + i] * inv * w[i], oh[b + i], ol[b + i]);
}

__global__ void rope_pack(const float* __restrict__ qkv,
                          __nv_bfloat16* __restrict__ qh, __nv_bfloat16* __restrict__ ql,
                          __nv_bfloat16* __restrict__ kh, __nv_bfloat16* __restrict__ kl) {
    int idx = blockIdx.x * 256 + threadIdx.x;   // over B*L*H*32
    int i = idx & 31;
    int rest = idx >> 5;
    int h = rest & (Hc - 1);
    int rl = rest >> 4;
    int l = rl & (Lc - 1);
    float ts = powf(10000.0f, (float)i * (1.0f / 32.0f));
    float ang = (float)l / ts;
    float sn = sinf(ang), cs = cosf(ang);
    long src = (long)rl * 3072 + h * DHc + i;
    long dst = (long)rl * Dc + h * DHc + i;
    float q1 = qkv[src], q2 = qkv[src + 32];
    packf2((q1 * cs - q2 * sn) * 0.125f, qh[dst], ql[dst]);
    packf2((q2 * cs + q1 * sn) * 0.125f, qh[dst + 32], ql[dst + 32]);
    float k1 = qkv[src + 1024], k2 = qkv[src + 1024 + 32];
    packf2(k1 * cs - k2 * sn, kh[dst], kl[dst]);
    packf2(k2 * cs + k1 * sn, kh[dst + 32], kl[dst + 32]);
}

__global__ void vtrans_pack(const float* __restrict__ qkv,
                            __nv_bfloat16* __restrict__ vh, __nv_bfloat16* __restrict__ vl) {
    __shared__ uint32_t t[32][33];
    int bh = blockIdx.z; int b = bh >> 4, h = bh & 15;
    int l0 = blockIdx.x * 32, d0 = blockIdx.y * 32;
    int tx = threadIdx.x, ty = threadIdx.y;
    float val = qkv[(long)(b * Lc + l0 + ty) * 3072 + 2048 + h * DHc + d0 + tx];
    t[ty][tx] = packf(val);
    __syncthreads();
    uint32_t p = t[tx][ty];
    long o = ((long)bh * DHc + d0 + ty) * Lc + l0 + tx;
    vh[o] = __ushort_as_bfloat16((unsigned short)(p & 0xFFFF));
    vl[o] = __ushort_as_bfloat16((unsigned short)(p >> 16));
}

__global__ void softmax_pack(const float* __restrict__ att,
                             __nv_bfloat16* __restrict__ oh, __nv_bfloat16* __restrict__ ol) {
    int qi = blockIdx.x;
    long base = ((long)blockIdx.y * Lc + qi) * Lc;
    int tid = threadIdx.x;
    float vals[4];
    float mx = -FLT_MAX;
    #pragma unroll
    for (int j = 0; j < 4; j++) {
        int kk = tid + j * 256;
        vals[j] = (kk <= qi) ? att[base + kk] : -FLT_MAX;
        mx = fmaxf(mx, vals[j]);
    }
    mx = blockReduceMax(mx);
    float s = 0.0f;
    #pragma unroll
    for (int j = 0; j < 4; j++) {
        int kk = tid + j * 256;
        if (kk <= qi) { vals[j] = expf(vals[j] - mx); s += vals[j]; }
        else vals[j] = 0.0f;
    }
    s = blockReduceSum(s);
    float inv = 1.0f / s;
    int lim = (qi | 127) + 1;
    #pragma unroll
    for (int j = 0; j < 4; j++) {
        int kk = tid + j * 256;
        if (kk < lim) packf2(vals[j] * inv, oh[base + kk], ol[base + kk]);
    }
}

__global__ void swish_pack(const float* __restrict__ gp,
                           __nv_bfloat16* __restrict__ oh, __nv_bfloat16* __restrict__ ol) {
    int i = blockIdx.x * 256 + threadIdx.x;     // over 2048*4096
    int row = i >> 12, col = i & 4095;
    float gv = gp[(long)row * 8192 + col];
    float pv = gp[(long)row * 8192 + 4096 + col];
    packf2(gv / (1.0f + expf(-gv)) * pv, oh[i], ol[i]);
}

// Transpose + split-pack: W [Kd][Nd] fp32 -> planes [Nd][Kd].
// block (8,32): float4 loads along Nd, ushort4 stores along Kd.
__global__ void wtrans(const float* __restrict__ W,
                       __nv_bfloat16* __restrict__ Oh, __nv_bfloat16* __restrict__ Ol,
                       int Kd, int Nd, long ostride) {
    __shared__ uint32_t t[32][33];
    long li = (long)blockIdx.z * Kd * Nd;
    long lo_ = (long)blockIdx.z * ostride;
    int n0 = blockIdx.x * 32, k0 = blockIdx.y * 32;
    int tx = threadIdx.x;   // 0..7
    int ty = threadIdx.y;   // 0..31
    float4 v = *(const float4*)(W + li + (long)(k0 + ty) * Nd + n0 + tx * 4);
    t[tx * 4 + 0][ty] = packf(v.x);
    t[tx * 4 + 1][ty] = packf(v.y);
    t[tx * 4 + 2][ty] = packf(v.z);
    t[tx * 4 + 3][ty] = packf(v.w);
    __syncthreads();
    uint32_t p0 = t[ty][tx * 4], p1 = t[ty][tx * 4 + 1], p2 = t[ty][tx * 4 + 2], p3 = t[ty][tx * 4 + 3];
    ushort4 hs = make_ushort4((unsigned short)(p0 & 0xFFFF), (unsigned short)(p1 & 0xFFFF),
                              (unsigned short)(p2 & 0xFFFF), (unsigned short)(p3 & 0xFFFF));
    ushort4 ls = make_ushort4((unsigned short)(p0 >> 16), (unsigned short)(p1 >> 16),
                              (unsigned short)(p2 >> 16), (unsigned short)(p3 >> 16));
    long o = lo_ + (long)(n0 + ty) * Kd + k0 + tx * 4;
    *(ushort4*)(Oh + o) = hs;
    *(ushort4*)(Ol + o) = ls;
}

// ---------------------------------------------------------------------------
// Host
// ---------------------------------------------------------------------------
#define SM128 (2 * (20480 + 128 * 160))   // 81920
#define SM64  (2 * (20480 + 64 * 160))    // 61440

extern "C" void kernel_launch(void* const* d_in, const int* in_sizes, int n_in,
                              void* d_out, int out_size) {
    const int*   tokens = (const int*)d_in[0];
    const float* embed  = (const float*)d_in[1];
    const float* ln1    = (const float*)d_in[2];
    const float* Wq     = (const float*)d_in[3];
    const float* Wk     = (const float*)d_in[4];
    const float* Wv     = (const float*)d_in[5];
    const float* Wo     = (const float*)d_in[6];
    const float* ln2    = (const float*)d_in[7];
    const float* Wg     = (const float*)d_in[8];
    const float* Wp     = (const float*)d_in[9];
    const float* Wd     = (const float*)d_in[10];
    const float* out_ln = (const float*)d_in[11];
    const float* head   = (const float*)d_in[12];

    cudaFuncSetAttribute(gemm_mma<128>, cudaFuncAttributeMaxDynamicSharedMemorySize, SM128);
    cudaFuncSetAttribute(gemm_mma<64>,  cudaFuncAttributeMaxDynamicSharedMemorySize, SM64);

    float *y, *qkv, *att, *gp;
    __nv_bfloat16 *xh, *xl, *qh, *ql, *kh, *kl, *vth, *vtl, *th, *tl, *ph, *pl, *gh, *gl, *wh, *wl;
    cudaGetSymbolAddress((void**)&y,   g_y);
    cudaGetSymbolAddress((void**)&qkv, g_qkv);
    cudaGetSymbolAddress((void**)&att, g_att);
    cudaGetSymbolAddress((void**)&gp,  g_gp);
    cudaGetSymbolAddress((void**)&xh,  g_xh);  cudaGetSymbolAddress((void**)&xl, g_xl);
    cudaGetSymbolAddress((void**)&qh,  g_qh);  cudaGetSymbolAddress((void**)&ql, g_ql);
    cudaGetSymbolAddress((void**)&kh,  g_kh);  cudaGetSymbolAddress((void**)&kl, g_kl);
    cudaGetSymbolAddress((void**)&vth, g_vth); cudaGetSymbolAddress((void**)&vtl, g_vtl);
    cudaGetSymbolAddress((void**)&th,  g_th);  cudaGetSymbolAddress((void**)&tl, g_tl);
    cudaGetSymbolAddress((void**)&ph,  g_ph);  cudaGetSymbolAddress((void**)&pl, g_pl);
    cudaGetSymbolAddress((void**)&gh,  g_gh);  cudaGetSymbolAddress((void**)&gl, g_gl);
    cudaGetSymbolAddress((void**)&wh,  g_wh);  cudaGetSymbolAddress((void**)&wl, g_wl);

    // weight layout (elements per plane)
    const long OQKV = 0;                       // 8 x [3072 x 1024]
    const long OO   = 25165824;                // 8 x [1024 x 1024]
    const long OGP  = 33554432;                // 8 x [8192 x 1024]
    const long OD   = 100663296;               // 8 x [1024 x 4096]
    const long OH   = 134217728;               // [32000 x 1024]

    const long LL = (long)Lc * Lc;   // 1048576
    const long LD = (long)Lc * Dc;   // 1048576
    dim3 tw(8, 32);
    dim3 tb(32, 32);

    // Launch order chosen so launch index 5 (0-based, after -s 5) is the
    // layer-0 QKV GEMM — gives ncu a gemm_mma<128> profile.
    embed_k<<<Bc * Lc, 256>>>(tokens, embed, y);                                              // 0
    wtrans<<<dim3(32, 32, 8), tw>>>(Wq, wh + OQKV,           wl + OQKV,           1024, 1024, 3145728);  // 1
    wtrans<<<dim3(32, 32, 8), tw>>>(Wk, wh + OQKV + 1048576, wl + OQKV + 1048576, 1024, 1024, 3145728);  // 2
    wtrans<<<dim3(32, 32, 8), tw>>>(Wv, wh + OQKV + 2097152, wl + OQKV + 2097152, 1024, 1024, 3145728);  // 3
    rmsnorm_pack<<<Bc * Lc, 256>>>(y, ln1, xh, xl);                                           // 4
    gemm_mma<128><<<dim3(24, 16, 1), 128, SM128>>>(                                           // 5 (profiled)
        xh, xl, wh + OQKV, wl + OQKV,
        qkv, 0, 0, 0, 1024, 1024, 1024, 3072, 1, 0, 0, 0, 0, 0, 0, 0);
    // remaining weight transposes (complete before their first use; same stream)
    wtrans<<<dim3(32, 32, 8),   tw>>>(Wo, wh + OO,            wl + OO,            1024, 1024, 1048576);
    wtrans<<<dim3(128, 32, 8),  tw>>>(Wg, wh + OGP,           wl + OGP,           1024, 4096, 8388608);
    wtrans<<<dim3(128, 32, 8),  tw>>>(Wp, wh + OGP + 4194304, wl + OGP + 4194304, 1024, 4096, 8388608);
    wtrans<<<dim3(32, 128, 8),  tw>>>(Wd, wh + OD,            wl + OD,            4096, 1024, 4194304);
    wtrans<<<dim3(1000, 32, 1), tw>>>(head, wh + OH,          wl + OH,            1024, 32000, 0);

    for (int l = 0; l < NL; l++) {
        if (l > 0) {
            rmsnorm_pack<<<Bc * Lc, 256>>>(y, ln1 + (long)l * Dc, xh, xl);
            gemm_mma<128><<<dim3(24, 16, 1), 128, SM128>>>(
                xh, xl, wh + OQKV + (long)l * 3145728, wl + OQKV + (long)l * 3145728,
                qkv, 0, 0, 0, 1024, 1024, 1024, 3072, 1, 0, 0, 0, 0, 0, 0, 0);
        }

        rope_pack<<<4096, 256>>>(qkv, qh, ql, kh, kl);
        vtrans_pack<<<dim3(32, 2, 32), tb>>>(qkv, vth, vtl);

        // scores (causal tiles skipped)
        gemm_mma<128><<<dim3(8, 8, 32), 128, SM128>>>(
            qh, ql, kh, kl, att, 0, 0, 0,
            64, 1024, 1024, 1024, Hc,
            LD, 64, LD, 64, (long)Hc * LL, LL, 2);

        softmax_pack<<<dim3(Lc, Bc * Hc), 256>>>(att, ph, pl);

        // AV (K clipped per M-tile), packed output planes
        gemm_mma<64><<<dim3(1, 8, 32), 128, SM64>>>(
            ph, pl, vth, vtl, 0, th, tl, 0,
            1024, 1024, 1024, 1024, Hc,
            (long)Hc * LL, LL, (long)Hc * DHc * Lc, (long)DHc * Lc, LD, 64, 4);

        // y += t @ Wo  (BN=64: 256 blocks -> 2 CTAs/SM, 86% wave fill)
        gemm_mma<64><<<dim3(16, 16, 1), 128, SM64>>>(
            th, tl, wh + OO + (long)l * 1048576, wl + OO + (long)l * 1048576,
            y, 0, 0, y, 1024, 1024, 1024, 1024, 1, 0, 0, 0, 0, 0, 0, 0);

        rmsnorm_pack<<<Bc * Lc, 256>>>(y, ln2 + (long)l * Dc, xh, xl);

        // merged gate+proj: [2048 x 8192]
        gemm_mma<128><<<dim3(64, 16, 1), 128, SM128>>>(
            xh, xl, wh + OGP + (long)l * 8388608, wl + OGP + (long)l * 8388608,
            gp, 0, 0, 0, 1024, 1024, 1024, 8192, 1, 0, 0, 0, 0, 0, 0, 0);

        swish_pack<<<32768, 256>>>(gp, gh, gl);

        // y += h @ Wd  (BN=64: 256 blocks)
        gemm_mma<64><<<dim3(16, 16, 1), 128, SM64>>>(
            gh, gl, wh + OD + (long)l * 4194304, wl + OD + (long)l * 4194304,
            y, 0, 0, y, 4096, 4096, 4096, 1024, 1, 0, 0, 0, 0, 0, 0, 0);
    }

    rmsnorm_pack<<<Bc * Lc, 256>>>(y, out_ln, xh, xl);
    gemm_mma<128><<<dim3(250, 16, 1), 128, SM128>>>(
        xh, xl, wh + OH, wl + OH, (float*)d_out, 0, 0, 0,
        1024, 1024, 1024, 32000, 1, 0, 0, 0, 0, 0, 0, 0);
}

// round 10
// speedup vs baseline: 1.0416x; 1.0416x over previous
#include <cuda_runtime.h>
#include <cuda_bf16.h>
#include <mma.h>
#include <math.h>
#include <float.h>
#include <stdint.h>

using namespace nvcuda;

#define Bc 2
#define Lc 1024
#define Dc 1024
#define Hc 16
#define NL 8
#define Vc 32000
#define Fc 4096
#define DHc 64

// ---------------------------------------------------------------------------
// Device-global scratch
// ---------------------------------------------------------------------------
__device__ float g_y[Bc*Lc*Dc];
__device__ float g_qkv[Bc*Lc*3*Dc];
__device__ float g_att[Bc*Hc*Lc*Lc];     // also reused as split-K partial buffers
__device__ float g_gp[Bc*Lc*2*Fc];
// bf16 hi/lo planes
__device__ __nv_bfloat16 g_xh[Bc*Lc*Dc],  g_xl[Bc*Lc*Dc];
__device__ __nv_bfloat16 g_qh[Bc*Lc*Dc],  g_ql[Bc*Lc*Dc];
__device__ __nv_bfloat16 g_kh[Bc*Lc*Dc],  g_kl[Bc*Lc*Dc];
__device__ __nv_bfloat16 g_vth[Bc*Hc*DHc*Lc], g_vtl[Bc*Hc*DHc*Lc];
__device__ __nv_bfloat16 g_th[Bc*Lc*Dc],  g_tl[Bc*Lc*Dc];
__device__ __nv_bfloat16 g_ph[Bc*Hc*Lc*Lc], g_pl[Bc*Hc*Lc*Lc];
__device__ __nv_bfloat16 g_gh[Bc*Lc*Fc],  g_gl[Bc*Lc*Fc];
__device__ __nv_bfloat16 g_wh[166985728], g_wl[166985728];

__device__ __forceinline__ uint32_t packf(float v) {
    __nv_bfloat16 h = __float2bfloat16(v);
    float hf = __bfloat162float(h);
    __nv_bfloat16 l = __float2bfloat16(v - hf);
    return (uint32_t)__bfloat16_as_ushort(h) | ((uint32_t)__bfloat16_as_ushort(l) << 16);
}
__device__ __forceinline__ void packf2(float v, __nv_bfloat16& h, __nv_bfloat16& l) {
    h = __float2bfloat16(v);
    l = __float2bfloat16(v - __bfloat162float(h));
}

__device__ __forceinline__ uint32_t smem_u32(const void* p) {
    uint32_t a;
    asm("{ .reg .u64 t; cvta.to.shared.u64 t, %1; cvt.u32.u64 %0, t; }" : "=r"(a) : "l"(p));
    return a;
}
__device__ __forceinline__ void cpasync16(uint32_t dst, const void* src) {
    asm volatile("cp.async.cg.shared.global [%0], [%1], 16;" :: "r"(dst), "l"(src) : "memory");
}
__device__ __forceinline__ void cp_commit() {
    asm volatile("cp.async.commit_group;" ::: "memory");
}
__device__ __forceinline__ void cp_wait1() {
    asm volatile("cp.async.wait_group 1;" ::: "memory");
}

// ---------------------------------------------------------------------------
// Block reductions (blockDim.x == 256)
// ---------------------------------------------------------------------------
__device__ __forceinline__ float blockReduceSum(float v) {
    __shared__ float sh[33];
    int lane = threadIdx.x & 31, wid = threadIdx.x >> 5;
    #pragma unroll
    for (int o = 16; o > 0; o >>= 1) v += __shfl_down_sync(0xffffffffu, v, o);
    if (lane == 0) sh[wid] = v;
    __syncthreads();
    v = (threadIdx.x < 8) ? sh[lane] : 0.0f;
    if (wid == 0) {
        #pragma unroll
        for (int o = 4; o > 0; o >>= 1) v += __shfl_down_sync(0xffffffffu, v, o);
        if (lane == 0) sh[32] = v;
    }
    __syncthreads();
    return sh[32];
}
__device__ __forceinline__ float blockReduceMax(float v) {
    __shared__ float sh[33];
    int lane = threadIdx.x & 31, wid = threadIdx.x >> 5;
    #pragma unroll
    for (int o = 16; o > 0; o >>= 1) v = fmaxf(v, __shfl_down_sync(0xffffffffu, v, o));
    if (lane == 0) sh[wid] = v;
    __syncthreads();
    v = (threadIdx.x < 8) ? sh[lane] : -FLT_MAX;
    if (wid == 0) {
        #pragma unroll
        for (int o = 4; o > 0; o >>= 1) v = fmaxf(v, __shfl_down_sync(0xffffffffu, v, o));
        if (lane == 0) sh[32] = v;
    }
    __syncthreads();
    return sh[32];
}

// ---------------------------------------------------------------------------
// WMMA GEMM, cp.async 2-stage pipeline, 128-thread CTAs (4 warps, 2Mx2N),
// warp tile 64 x (BN/2), 2 CTAs/SM.
// D[M,N] = A[M,K] @ B[N,K]^T, bf16x3 (hi*hi + hi*lo + lo*hi), fp32 accum.
// A,B: separate hi/lo bf16 planes, K-major. BM=128, BK=32.
// flags: bit1 = causal tile skip, bit2 = K clip to row0+128.
// Ch != null -> bf16 hi/lo output planes; else fp32 C (R folded into acc init).
// Split-K is expressed via the batch machinery: gridDim.z = nsplit, bH = 1,
// sAb = sBb = K_half (element offsets within the K-major rows), sCb = M*N.
// ---------------------------------------------------------------------------
#define LDS_ 40     // smem row pitch in bf16 elems (64B data + 16B pad)

template<int BN>
__global__ __launch_bounds__(128, 2) void gemm_mma(
    const __nv_bfloat16* __restrict__ Ahp, const __nv_bfloat16* __restrict__ Alp,
    const __nv_bfloat16* __restrict__ Bhp, const __nv_bfloat16* __restrict__ Blp,
    float* __restrict__ C, __nv_bfloat16* __restrict__ Ch, __nv_bfloat16* __restrict__ Cl,
    const float* __restrict__ R,
    int K, int lda, int ldb, int ldc, int bH,
    long sAb, long sAh, long sBb, long sBh, long sCb, long sCh, int flags)
{
    const int BM = 128;
    const int WN = BN / 2;           // warp N span
    const int NT = WN / 16;          // 16-col tiles per warp (4 or 2)
    const int APB = 5120;            // A plane elems in smem (128*40)
    const int BPB = BN * LDS_;
    const int SSZ = (2 * APB + 2 * BPB) * 2;   // stage bytes

    int row0 = blockIdx.y * BM, col0 = blockIdx.x * BN;
    if ((flags & 2) && col0 >= row0 + BM) return;
    if (flags & 4) { int kc = row0 + BM; if (kc < K) K = kc; }
    int z = blockIdx.z, zb = z / bH, zh = z - zb * bH;
    long aoff = (long)zb * sAb + (long)zh * sAh;
    long boff = (long)zb * sBb + (long)zh * sBh;
    long coff = (long)zb * sCb + (long)zh * sCh;

    extern __shared__ __align__(16) char smraw[];
    uint32_t sbase = smem_u32(smraw);

    int tid = threadIdx.x, wid = tid >> 5, lane = tid & 31;
    int wm = wid & 1, wn = wid >> 1;

    wmma::fragment<wmma::accumulator, 16, 16, 16, float> acc[4][NT];
    if (R) {
        const float* Rb = R + coff;
        #pragma unroll
        for (int i = 0; i < 4; i++)
            #pragma unroll
            for (int j = 0; j < NT; j++)
                wmma::load_matrix_sync(acc[i][j],
                    Rb + (long)(row0 + wm * 64 + i * 16) * ldc + col0 + wn * WN + j * 16,
                    ldc, wmma::mem_row_major);
    } else {
        #pragma unroll
        for (int i = 0; i < 4; i++)
            #pragma unroll
            for (int j = 0; j < NT; j++)
                wmma::fill_fragment(acc[i][j], 0.0f);
    }

    const __nv_bfloat16* Ahg = Ahp + aoff + (long)row0 * lda;
    const __nv_bfloat16* Alg = Alp + aoff + (long)row0 * lda;
    const __nv_bfloat16* Bhg = Bhp + boff + (long)col0 * ldb;
    const __nv_bfloat16* Blg = Blp + boff + (long)col0 * ldb;
    int NC = K >> 5;

    auto issue = [&](int c) {
        uint32_t sb = sbase + (c & 1) * SSZ;
        int kc = c << 5;
        #pragma unroll
        for (int i = 0; i < 4; i++) {
            int lin = tid + i * 128;
            int r = lin >> 2, g = lin & 3;
            long go = (long)r * lda + kc + g * 8;
            uint32_t so = r * 80 + g * 16;
            cpasync16(sb + so, Ahg + go);
            cpasync16(sb + 2 * APB + so, Alg + go);
        }
        #pragma unroll
        for (int i = 0; i < BN / 32; i++) {
            int lin = tid + i * 128;
            int r = lin >> 2, g = lin & 3;
            long go = (long)r * ldb + kc + g * 8;
            uint32_t so = r * 80 + g * 16;
            cpasync16(sb + 4 * APB + so, Bhg + go);
            cpasync16(sb + 4 * APB + 2 * BPB + so, Blg + go);
        }
    };

    issue(0); cp_commit();
    if (NC > 1) issue(1);
    cp_commit();

    for (int c = 0; c < NC; c++) {
        cp_wait1();
        __syncthreads();
        {
            const __nv_bfloat16* base = (const __nv_bfloat16*)(smraw + (c & 1) * SSZ);
            const __nv_bfloat16* Ah = base;
            const __nv_bfloat16* Al = base + APB;
            const __nv_bfloat16* Bh = base + 2 * APB;
            const __nv_bfloat16* Bl = base + 2 * APB + BPB;
            #pragma unroll
            for (int ks = 0; ks < 2; ks++) {
                int k0 = ks * 16;
                wmma::fragment<wmma::matrix_b, 16, 16, 16, __nv_bfloat16, wmma::col_major> fbh[NT], fbl[NT];
                #pragma unroll
                for (int j = 0; j < NT; j++) {
                    wmma::load_matrix_sync(fbh[j], Bh + (wn * WN + j * 16) * LDS_ + k0, LDS_);
                    wmma::load_matrix_sync(fbl[j], Bl + (wn * WN + j * 16) * LDS_ + k0, LDS_);
                }
                #pragma unroll
                for (int i = 0; i < 4; i++) {
                    wmma::fragment<wmma::matrix_a, 16, 16, 16, __nv_bfloat16, wmma::row_major> fah, fal;
                    wmma::load_matrix_sync(fah, Ah + (wm * 64 + i * 16) * LDS_ + k0, LDS_);
                    wmma::load_matrix_sync(fal, Al + (wm * 64 + i * 16) * LDS_ + k0, LDS_);
                    #pragma unroll
                    for (int j = 0; j < NT; j++) {
                        wmma::mma_sync(acc[i][j], fah, fbh[j], acc[i][j]);
                        wmma::mma_sync(acc[i][j], fah, fbl[j], acc[i][j]);
                        wmma::mma_sync(acc[i][j], fal, fbh[j], acc[i][j]);
                    }
                }
            }
        }
        __syncthreads();
        if (c + 2 < NC) issue(c + 2);
        cp_commit();
    }

    // ---- epilogue ----
    if (!Ch) {
        float* Cb = C + coff;
        #pragma unroll
        for (int i = 0; i < 4; i++)
            #pragma unroll
            for (int j = 0; j < NT; j++)
                wmma::store_matrix_sync(
                    Cb + (long)(row0 + wm * 64 + i * 16) * ldc + col0 + wn * WN + j * 16,
                    acc[i][j], ldc, wmma::mem_row_major);
    } else {
        __syncthreads();
        float* wbuf = (float*)smraw + wid * 256;
        #pragma unroll
        for (int i = 0; i < 4; i++)
            #pragma unroll
            for (int j = 0; j < NT; j++) {
                wmma::store_matrix_sync(wbuf, acc[i][j], 16, wmma::mem_row_major);
                __syncwarp();
                int r = lane >> 1, chn = lane & 1;
                const float* src = wbuf + r * 16 + chn * 8;
                __nv_bfloat16 hb[8], lb[8];
                #pragma unroll
                for (int t = 0; t < 8; t++) packf2(src[t], hb[t], lb[t]);
                long off = (long)(row0 + wm * 64 + i * 16 + r) * ldc + col0 + wn * WN + j * 16 + chn * 8 + coff;
                *(uint4*)(Ch + off) = *(uint4*)hb;
                *(uint4*)(Cl + off) = *(uint4*)lb;
                __syncwarp();
            }
    }
}

// ---------------------------------------------------------------------------
// Split-K reduction: y[i] = y[i] + p0[i] + p1[i]   (vectorized)
// ---------------------------------------------------------------------------
__global__ void reduce_k(float* __restrict__ y, const float* __restrict__ p0,
                         const float* __restrict__ p1) {
    int i = blockIdx.x * 256 + threadIdx.x;     // over (B*L*D)/4
    float4 a = ((const float4*)y)[i];
    float4 b = ((const float4*)p0)[i];
    float4 c = ((const float4*)p1)[i];
    a.x += b.x + c.x; a.y += b.y + c.y; a.z += b.z + c.z; a.w += b.w + c.w;
    ((float4*)y)[i] = a;
}

// ---------------------------------------------------------------------------
// Aux kernels
// ---------------------------------------------------------------------------
__global__ void embed_k(const int* __restrict__ tokens, const float* __restrict__ emb,
                        float* __restrict__ y) {
    int r = blockIdx.x;
    int tok = tokens[r];
    const float4* src = (const float4*)(emb + (long)tok * Dc);
    float4* dst = (float4*)(y + (long)r * Dc);
    for (int i = threadIdx.x; i < Dc / 4; i += blockDim.x) dst[i] = src[i];
}

__global__ void rmsnorm_pack(const float* __restrict__ in, const float* __restrict__ w,
                             __nv_bfloat16* __restrict__ oh, __nv_bfloat16* __restrict__ ol) {
    long b = (long)blockIdx.x * Dc;
    float s = 0.0f;
    for (int i = threadIdx.x; i < Dc; i += 256) { float v = in[b + i]; s += v * v; }
    s = blockReduceSum(s);
    float inv = rsqrtf(s * (1.0f / Dc) + 1e-6f);
    for (int i = threadIdx.x; i < Dc; i += 256)
        packf2(in[b + i] * inv * w[i], oh[b + i], ol[b + i]);
}

__global__ void rope_pack(const float* __restrict__ qkv,
                          __nv_bfloat16* __restrict__ qh, __nv_bfloat16* __restrict__ ql,
                          __nv_bfloat16* __restrict__ kh, __nv_bfloat16* __restrict__ kl) {
    int idx = blockIdx.x * 256 + threadIdx.x;   // over B*L*H*32
    int i = idx & 31;
    int rest = idx >> 5;
    int h = rest & (Hc - 1);
    int rl = rest >> 4;
    int l = rl & (Lc - 1);
    float ts = powf(10000.0f, (float)i * (1.0f / 32.0f));
    float ang = (float)l / ts;
    float sn = sinf(ang), cs = cosf(ang);
    long src = (long)rl * 3072 + h * DHc + i;
    long dst = (long)rl * Dc + h * DHc + i;
    float q1 = qkv[src], q2 = qkv[src + 32];
    packf2((q1 * cs - q2 * sn) * 0.125f, qh[dst], ql[dst]);
    packf2((q2 * cs + q1 * sn) * 0.125f, qh[dst + 32], ql[dst + 32]);
    float k1 = qkv[src + 1024], k2 = qkv[src + 1024 + 32];
    packf2(k1 * cs - k2 * sn, kh[dst], kl[dst]);
    packf2(k2 * cs + k1 * sn, kh[dst + 32], kl[dst + 32]);
}

__global__ void vtrans_pack(const float* __restrict__ qkv,
                            __nv_bfloat16* __restrict__ vh, __nv_bfloat16* __restrict__ vl) {
    __shared__ uint32_t t[32][33];
    int bh = blockIdx.z; int b = bh >> 4, h = bh & 15;
    int l0 = blockIdx.x * 32, d0 = blockIdx.y * 32;
    int tx = threadIdx.x, ty = threadIdx.y;
    float val = qkv[(long)(b * Lc + l0 + ty) * 3072 + 2048 + h * DHc + d0 + tx];
    t[ty][tx] = packf(val);
    __syncthreads();
    uint32_t p = t[tx][ty];
    long o = ((long)bh * DHc + d0 + ty) * Lc + l0 + tx;
    vh[o] = __ushort_as_bfloat16((unsigned short)(p & 0xFFFF));
    vl[o] = __ushort_as_bfloat16((unsigned short)(p >> 16));
}

__global__ void softmax_pack(const float* __restrict__ att,
                             __nv_bfloat16* __restrict__ oh, __nv_bfloat16* __restrict__ ol) {
    int qi = blockIdx.x;
    long base = ((long)blockIdx.y * Lc + qi) * Lc;
    int tid = threadIdx.x;
    float vals[4];
    float mx = -FLT_MAX;
    #pragma unroll
    for (int j = 0; j < 4; j++) {
        int kk = tid + j * 256;
        vals[j] = (kk <= qi) ? att[base + kk] : -FLT_MAX;
        mx = fmaxf(mx, vals[j]);
    }
    mx = blockReduceMax(mx);
    float s = 0.0f;
    #pragma unroll
    for (int j = 0; j < 4; j++) {
        int kk = tid + j * 256;
        if (kk <= qi) { vals[j] = expf(vals[j] - mx); s += vals[j]; }
        else vals[j] = 0.0f;
    }
    s = blockReduceSum(s);
    float inv = 1.0f / s;
    int lim = (qi | 127) + 1;
    #pragma unroll
    for (int j = 0; j < 4; j++) {
        int kk = tid + j * 256;
        if (kk < lim) packf2(vals[j] * inv, oh[base + kk], ol[base + kk]);
    }
}

__global__ void swish_pack(const float* __restrict__ gp,
                           __nv_bfloat16* __restrict__ oh, __nv_bfloat16* __restrict__ ol) {
    int i = blockIdx.x * 256 + threadIdx.x;     // over 2048*4096
    int row = i >> 12, col = i & 4095;
    float gv = gp[(long)row * 8192 + col];
    float pv = gp[(long)row * 8192 + 4096 + col];
    packf2(gv / (1.0f + expf(-gv)) * pv, oh[i], ol[i]);
}

// Transpose + split-pack: W [Kd][Nd] fp32 -> planes [Nd][Kd].
// block (8,32): float4 loads along Nd, ushort4 stores along Kd.
__global__ void wtrans(const float* __restrict__ W,
                       __nv_bfloat16* __restrict__ Oh, __nv_bfloat16* __restrict__ Ol,
                       int Kd, int Nd, long ostride) {
    __shared__ uint32_t t[32][33];
    long li = (long)blockIdx.z * Kd * Nd;
    long lo_ = (long)blockIdx.z * ostride;
    int n0 = blockIdx.x * 32, k0 = blockIdx.y * 32;
    int tx = threadIdx.x;   // 0..7
    int ty = threadIdx.y;   // 0..31
    float4 v = *(const float4*)(W + li + (long)(k0 + ty) * Nd + n0 + tx * 4);
    t[tx * 4 + 0][ty] = packf(v.x);
    t[tx * 4 + 1][ty] = packf(v.y);
    t[tx * 4 + 2][ty] = packf(v.z);
    t[tx * 4 + 3][ty] = packf(v.w);
    __syncthreads();
    uint32_t p0 = t[ty][tx * 4], p1 = t[ty][tx * 4 + 1], p2 = t[ty][tx * 4 + 2], p3 = t[ty][tx * 4 + 3];
    ushort4 hs = make_ushort4((unsigned short)(p0 & 0xFFFF), (unsigned short)(p1 & 0xFFFF),
                              (unsigned short)(p2 & 0xFFFF), (unsigned short)(p3 & 0xFFFF));
    ushort4 ls = make_ushort4((unsigned short)(p0 >> 16), (unsigned short)(p1 >> 16),
                              (unsigned short)(p2 >> 16), (unsigned short)(p3 >> 16));
    long o = lo_ + (long)(n0 + ty) * Kd + k0 + tx * 4;
    *(ushort4*)(Oh + o) = hs;
    *(ushort4*)(Ol + o) = ls;
}

// ---------------------------------------------------------------------------
// Host
// ---------------------------------------------------------------------------
#define SM128 (2 * (20480 + 128 * 160))   // 81920
#define SM64  (2 * (20480 + 64 * 160))    // 61440

extern "C" void kernel_launch(void* const* d_in, const int* in_sizes, int n_in,
                              void* d_out, int out_size) {
    const int*   tokens = (const int*)d_in[0];
    const float* embed  = (const float*)d_in[1];
    const float* ln1    = (const float*)d_in[2];
    const float* Wq     = (const float*)d_in[3];
    const float* Wk     = (const float*)d_in[4];
    const float* Wv     = (const float*)d_in[5];
    const float* Wo     = (const float*)d_in[6];
    const float* ln2    = (const float*)d_in[7];
    const float* Wg     = (const float*)d_in[8];
    const float* Wp     = (const float*)d_in[9];
    const float* Wd     = (const float*)d_in[10];
    const float* out_ln = (const float*)d_in[11];
    const float* head   = (const float*)d_in[12];

    cudaFuncSetAttribute(gemm_mma<128>, cudaFuncAttributeMaxDynamicSharedMemorySize, SM128);
    cudaFuncSetAttribute(gemm_mma<64>,  cudaFuncAttributeMaxDynamicSharedMemorySize, SM64);

    float *y, *qkv, *att, *gp;
    __nv_bfloat16 *xh, *xl, *qh, *ql, *kh, *kl, *vth, *vtl, *th, *tl, *ph, *pl, *gh, *gl, *wh, *wl;
    cudaGetSymbolAddress((void**)&y,   g_y);
    cudaGetSymbolAddress((void**)&qkv, g_qkv);
    cudaGetSymbolAddress((void**)&att, g_att);
    cudaGetSymbolAddress((void**)&gp,  g_gp);
    cudaGetSymbolAddress((void**)&xh,  g_xh);  cudaGetSymbolAddress((void**)&xl, g_xl);
    cudaGetSymbolAddress((void**)&qh,  g_qh);  cudaGetSymbolAddress((void**)&ql, g_ql);
    cudaGetSymbolAddress((void**)&kh,  g_kh);  cudaGetSymbolAddress((void**)&kl, g_kl);
    cudaGetSymbolAddress((void**)&vth, g_vth); cudaGetSymbolAddress((void**)&vtl, g_vtl);
    cudaGetSymbolAddress((void**)&th,  g_th);  cudaGetSymbolAddress((void**)&tl, g_tl);
    cudaGetSymbolAddress((void**)&ph,  g_ph);  cudaGetSymbolAddress((void**)&pl, g_pl);
    cudaGetSymbolAddress((void**)&gh,  g_gh);  cudaGetSymbolAddress((void**)&gl, g_gl);
    cudaGetSymbolAddress((void**)&wh,  g_wh);  cudaGetSymbolAddress((void**)&wl, g_wl);

    // weight layout (elements per plane)
    const long OQKV = 0;                       // 8 x [3072 x 1024]
    const long OO   = 25165824;                // 8 x [1024 x 1024]
    const long OGP  = 33554432;                // 8 x [8192 x 1024]
    const long OD   = 100663296;               // 8 x [1024 x 4096]
    const long OH   = 134217728;               // [32000 x 1024]

    const long MD = (long)Bc * Lc * Dc;        // 2097152 (partial-buffer stride)
    float* part = att;                         // split-K partials alias free att scratch

    dim3 tw(8, 32);
    wtrans<<<dim3(32, 32, 8),   tw>>>(Wq, wh + OQKV,            wl + OQKV,            1024, 1024, 3145728);
    wtrans<<<dim3(32, 32, 8),   tw>>>(Wk, wh + OQKV + 1048576,  wl + OQKV + 1048576,  1024, 1024, 3145728);
    wtrans<<<dim3(32, 32, 8),   tw>>>(Wv, wh + OQKV + 2097152,  wl + OQKV + 2097152,  1024, 1024, 3145728);
    wtrans<<<dim3(32, 32, 8),   tw>>>(Wo, wh + OO,              wl + OO,              1024, 1024, 1048576);
    wtrans<<<dim3(128, 32, 8),  tw>>>(Wg, wh + OGP,             wl + OGP,             1024, 4096, 8388608);
    wtrans<<<dim3(128, 32, 8),  tw>>>(Wp, wh + OGP + 4194304,   wl + OGP + 4194304,   1024, 4096, 8388608);
    wtrans<<<dim3(32, 128, 8),  tw>>>(Wd, wh + OD,              wl + OD,              4096, 1024, 4194304);
    wtrans<<<dim3(1000, 32, 1), tw>>>(head, wh + OH,            wl + OH,              1024, 32000, 0);

    embed_k<<<Bc * Lc, 256>>>(tokens, embed, y);

    const long LL = (long)Lc * Lc;   // 1048576
    const long LD = (long)Lc * Dc;   // 1048576
    dim3 tb(32, 32);

    for (int l = 0; l < NL; l++) {
        rmsnorm_pack<<<Bc * Lc, 256>>>(y, ln1 + (long)l * Dc, xh, xl);

        // merged QKV: [2048 x 3072]
        gemm_mma<128><<<dim3(24, 16, 1), 128, SM128>>>(
            xh, xl, wh + OQKV + (long)l * 3145728, wl + OQKV + (long)l * 3145728,
            qkv, 0, 0, 0, 1024, 1024, 1024, 3072, 1, 0, 0, 0, 0, 0, 0, 0);

        rope_pack<<<4096, 256>>>(qkv, qh, ql, kh, kl);
        vtrans_pack<<<dim3(32, 2, 32), tb>>>(qkv, vth, vtl);

        // scores (causal tiles skipped)
        gemm_mma<128><<<dim3(8, 8, 32), 128, SM128>>>(
            qh, ql, kh, kl, att, 0, 0, 0,
            64, 1024, 1024, 1024, Hc,
            LD, 64, LD, 64, (long)Hc * LL, LL, 2);

        softmax_pack<<<dim3(Lc, Bc * Hc), 256>>>(att, ph, pl);

        // AV (K clipped per M-tile), packed output planes
        gemm_mma<64><<<dim3(1, 8, 32), 128, SM64>>>(
            ph, pl, vth, vtl, 0, th, tl, 0,
            1024, 1024, 1024, 1024, Hc,
            (long)Hc * LL, LL, (long)Hc * DHc * Lc, (long)DHc * Lc, LD, 64, 4);

        // Wo with split-K=2: grid z = split, K window via sAb/sBb offsets
        gemm_mma<128><<<dim3(8, 16, 2), 128, SM128>>>(
            th, tl, wh + OO + (long)l * 1048576, wl + OO + (long)l * 1048576,
            part, 0, 0, 0, 512, 1024, 1024, 1024, 1,
            512, 0, 512, 0, MD, 0, 0);
        reduce_k<<<(int)(MD / 1024), 256>>>(y, part, part + MD);

        rmsnorm_pack<<<Bc * Lc, 256>>>(y, ln2 + (long)l * Dc, xh, xl);

        // merged gate+proj: [2048 x 8192]
        gemm_mma<128><<<dim3(64, 16, 1), 128, SM128>>>(
            xh, xl, wh + OGP + (long)l * 8388608, wl + OGP + (long)l * 8388608,
            gp, 0, 0, 0, 1024, 1024, 1024, 8192, 1, 0, 0, 0, 0, 0, 0, 0);

        swish_pack<<<32768, 256>>>(gp, gh, gl);

        // Wd with split-K=2 (K = 4096 -> 2 x 2048)
        gemm_mma<128><<<dim3(8, 16, 2), 128, SM128>>>(
            gh, gl, wh + OD + (long)l * 4194304, wl + OD + (long)l * 4194304,
            part, 0, 0, 0, 2048, 4096, 4096, 1024, 1,
            2048, 0, 2048, 0, MD, 0, 0);
        reduce_k<<<(int)(MD / 1024), 256>>>(y, part, part + MD);
    }

    rmsnorm_pack<<<Bc * Lc, 256>>>(y, out_ln, xh, xl);
    gemm_mma<128><<<dim3(250, 16, 1), 128, SM128>>>(
        xh, xl, wh + OH, wl + OH, (float*)d_out, 0, 0, 0,
        1024, 1024, 1024, 32000, 1, 0, 0, 0, 0, 0, 0, 0);
}